// round 3
// baseline (speedup 1.0000x reference)
#include <cuda_runtime.h>
#include <math.h>

#define NNODE 8192
#define DDIM  256
#define NPG   256
#define BGRP  32
#define NEDGE 131072
#define NMASK (BGRP * NPG)
#define ZERO_EPS 1e-8f

#define BM 64
#define BN 64
#define BK 16
#define LDA_S 17
#define LDB_S 68

// ---------------- scratch (device globals; no allocation in kernel_launch) ---
__device__ float g_H0[NNODE * DDIM];            // 8 MB
__device__ float g_H1[NNODE * DDIM];            // 8 MB
__device__ float g_G[3 * NNODE * DDIM];         // 24 MB
__device__ float g_HT[NNODE * DDIM];            // 8 MB
__device__ float g_Ablk[BGRP * NPG * NPG];      // 8 MB  (block-diagonal A)
__device__ float g_Adj[3 * BGRP * NPG * NPG];   // 24 MB (dense per-group adjacency)
__device__ float g_nrm[NNODE];
__device__ float g_rinv[NNODE];
__device__ float g_sc[NNODE];                   // dinv_i / nrm_i
__device__ float g_svec[DDIM];                  // sum_j h_j / ||h_j||
__device__ float g_emf[NMASK];
__device__ float g_pmf[NMASK];
__device__ int   g_mask_mode;                   // 0=u8, 1=i32, 2=f32

// ---------------- tiled GEMM mainloops --------------------------------------
__device__ __forceinline__ void mm_nn(const float* __restrict__ Ag, int lda,
                                      const float* __restrict__ Bg, int ldb,
                                      int K,
                                      float (*As)[LDA_S], float (*Bs)[LDB_S],
                                      float acc[4][4])
{
    int tid = threadIdx.x;
    int tx = tid & 15, ty = tid >> 4;
    int a_m = tid >> 2, a_k = (tid & 3) << 2;
    int b_k = tid >> 4, b_n = (tid & 15) << 2;
    for (int k0 = 0; k0 < K; k0 += BK) {
        float4 av = *(const float4*)(Ag + (size_t)a_m * lda + k0 + a_k);
        float4 bv = *(const float4*)(Bg + (size_t)(k0 + b_k) * ldb + b_n);
        __syncthreads();
        As[a_m][a_k + 0] = av.x; As[a_m][a_k + 1] = av.y;
        As[a_m][a_k + 2] = av.z; As[a_m][a_k + 3] = av.w;
        Bs[b_k][b_n + 0] = bv.x; Bs[b_k][b_n + 1] = bv.y;
        Bs[b_k][b_n + 2] = bv.z; Bs[b_k][b_n + 3] = bv.w;
        __syncthreads();
        #pragma unroll
        for (int kk = 0; kk < BK; kk++) {
            float a0 = As[ty * 4 + 0][kk], a1 = As[ty * 4 + 1][kk];
            float a2 = As[ty * 4 + 2][kk], a3 = As[ty * 4 + 3][kk];
            float b0 = Bs[kk][tx * 4 + 0], b1 = Bs[kk][tx * 4 + 1];
            float b2 = Bs[kk][tx * 4 + 2], b3 = Bs[kk][tx * 4 + 3];
            acc[0][0] += a0 * b0; acc[0][1] += a0 * b1; acc[0][2] += a0 * b2; acc[0][3] += a0 * b3;
            acc[1][0] += a1 * b0; acc[1][1] += a1 * b1; acc[1][2] += a1 * b2; acc[1][3] += a1 * b3;
            acc[2][0] += a2 * b0; acc[2][1] += a2 * b1; acc[2][2] += a2 * b2; acc[2][3] += a2 * b3;
            acc[3][0] += a3 * b0; acc[3][1] += a3 * b1; acc[3][2] += a3 * b2; acc[3][3] += a3 * b3;
        }
    }
}

__device__ __forceinline__ void mm_nt(const float* __restrict__ Ag, int lda,
                                      const float* __restrict__ Bg, int ldb,
                                      int K,
                                      float (*As)[LDA_S], float (*Bs)[LDB_S],
                                      float acc[4][4])
{
    int tid = threadIdx.x;
    int tx = tid & 15, ty = tid >> 4;
    int a_m = tid >> 2, a_k = (tid & 3) << 2;
    int b_n = tid >> 2, b_k = (tid & 3) << 2;
    for (int k0 = 0; k0 < K; k0 += BK) {
        float4 av = *(const float4*)(Ag + (size_t)a_m * lda + k0 + a_k);
        float4 bv = *(const float4*)(Bg + (size_t)b_n * ldb + k0 + b_k);
        __syncthreads();
        As[a_m][a_k + 0] = av.x; As[a_m][a_k + 1] = av.y;
        As[a_m][a_k + 2] = av.z; As[a_m][a_k + 3] = av.w;
        Bs[b_k + 0][b_n] = bv.x; Bs[b_k + 1][b_n] = bv.y;
        Bs[b_k + 2][b_n] = bv.z; Bs[b_k + 3][b_n] = bv.w;
        __syncthreads();
        #pragma unroll
        for (int kk = 0; kk < BK; kk++) {
            float a0 = As[ty * 4 + 0][kk], a1 = As[ty * 4 + 1][kk];
            float a2 = As[ty * 4 + 2][kk], a3 = As[ty * 4 + 3][kk];
            float b0 = Bs[kk][tx * 4 + 0], b1 = Bs[kk][tx * 4 + 1];
            float b2 = Bs[kk][tx * 4 + 2], b3 = Bs[kk][tx * 4 + 3];
            acc[0][0] += a0 * b0; acc[0][1] += a0 * b1; acc[0][2] += a0 * b2; acc[0][3] += a0 * b3;
            acc[1][0] += a1 * b0; acc[1][1] += a1 * b1; acc[1][2] += a1 * b2; acc[1][3] += a1 * b3;
            acc[2][0] += a2 * b0; acc[2][1] += a2 * b1; acc[2][2] += a2 * b2; acc[2][3] += a2 * b3;
            acc[3][0] += a3 * b0; acc[3][1] += a3 * b1; acc[3][2] += a3 * b2; acc[3][3] += a3 * b3;
        }
    }
}

// ---------------- small kernels ---------------------------------------------
__global__ void k_zero(float* __restrict__ p, int n) {
    for (int i = blockIdx.x * blockDim.x + threadIdx.x; i < n; i += gridDim.x * blockDim.x)
        p[i] = 0.f;
}

// Detect mask element encoding by scanning the first NMASK BYTES only (always
// in-bounds regardless of true element width).
//   u8 bool 0/1 : nonzero bytes at all positions mod 4
//   i32 0/1     : nonzero only at pos%4==0
//   f32 0.0/1.0 : nonzero only at pos%4 in {2,3} (0x3F800000)
__global__ void k_mask_detect(const unsigned char* __restrict__ em,
                              const unsigned char* __restrict__ pm) {
    __shared__ int nz[4];
    if (threadIdx.x < 4) nz[threadIdx.x] = 0;
    __syncthreads();
    int loc[4] = {0, 0, 0, 0};
    for (int i = threadIdx.x; i < NMASK; i += 256) {
        if (em[i]) loc[i & 3]++;
        if (pm[i]) loc[i & 3]++;
    }
    #pragma unroll
    for (int j = 0; j < 4; j++) if (loc[j]) atomicAdd(&nz[j], loc[j]);
    __syncthreads();
    if (threadIdx.x == 0) {
        int mode;
        if (nz[1] > 0) mode = 0;            // bytes at odd positions -> u8
        else if (nz[0] > 0) mode = 1;       // only 4-aligned -> i32
        else mode = 2;                      // only pos 2/3 (or all zero) -> f32
        g_mask_mode = mode;
    }
}

__global__ void k_mask_decode(const unsigned char* __restrict__ em,
                              const unsigned char* __restrict__ pm,
                              float* __restrict__ emf, float* __restrict__ pmf) {
    int i = blockIdx.x * blockDim.x + threadIdx.x;
    if (i >= NMASK) return;
    int mode = g_mask_mode;
    float e, p;
    if (mode == 0) {
        e = em[i] ? 1.f : 0.f;
        p = pm[i] ? 1.f : 0.f;
    } else if (mode == 1) {
        e = ((const int*)em)[i] ? 1.f : 0.f;
        p = ((const int*)pm)[i] ? 1.f : 0.f;
    } else {
        e = (((const float*)em)[i] != 0.f) ? 1.f : 0.f;
        p = (((const float*)pm)[i] != 0.f) ? 1.f : 0.f;
    }
    emf[i] = e; pmf[i] = p;
}

__global__ void k_rownorm(const float* __restrict__ x, float* __restrict__ nrm,
                          float* __restrict__ rinv) {
    int warp = (blockIdx.x * blockDim.x + threadIdx.x) >> 5;
    int lane = threadIdx.x & 31;
    if (warp >= NNODE) return;
    const float* r = x + (size_t)warp * DDIM;
    float s = 0.f;
    for (int j = lane; j < DDIM; j += 32) { float v = r[j]; s += v * v; }
    #pragma unroll
    for (int o = 16; o; o >>= 1) s += __shfl_xor_sync(0xffffffffu, s, o);
    if (!lane) { float n = sqrtf(s); nrm[warp] = n; rinv[warp] = 1.0f / n; }
}

__global__ void k_colsum(const float* __restrict__ x, const float* __restrict__ rinv,
                         float* __restrict__ svec) {
    int d = threadIdx.x;        // 0..255
    int r0 = blockIdx.x * 128;  // 64 blocks * 128 rows
    float acc = 0.f;
    for (int r = r0; r < r0 + 128; r++)
        acc += x[(size_t)r * DDIM + d] * rinv[r];
    atomicAdd(&svec[d], acc);
}

__global__ void k_scale(const float* __restrict__ x, const float* __restrict__ rinv,
                        const float* __restrict__ svec, float* __restrict__ sc) {
    int warp = (blockIdx.x * blockDim.x + threadIdx.x) >> 5;
    int lane = threadIdx.x & 31;
    if (warp >= NNODE) return;
    const float* r = x + (size_t)warp * DDIM;
    float dot = 0.f;
    for (int j = lane; j < DDIM; j += 32) dot += r[j] * svec[j];
    #pragma unroll
    for (int o = 16; o; o >>= 1) dot += __shfl_xor_sync(0xffffffffu, dot, o);
    if (!lane) {
        float rowsum = dot * rinv[warp];
        sc[warp] = rsqrtf(fabsf(rowsum) + ZERO_EPS) * rinv[warp];
    }
}

// edge indices are int32
__global__ void k_scatter_w(const int* __restrict__ ei, const float* __restrict__ ew,
                            float* __restrict__ Adj) {
    int e = blockIdx.x * blockDim.x + threadIdx.x;
    if (e >= NEDGE) return;
    int src = ei[e], dst = ei[NEDGE + e];
    int b = src >> 8, sl = src & 255, dl = dst & 255;
    atomicAdd(&Adj[(((size_t)b << 8) + dl) * NPG + sl], ew[e]);
}

__global__ void k_scatter_A(const int* __restrict__ ei, const float* __restrict__ Ablk,
                            float* __restrict__ Adj) {
    int e = blockIdx.x * blockDim.x + threadIdx.x;
    if (e >= NEDGE) return;
    int src = ei[e], dst = ei[NEDGE + e];
    int b = src >> 8, sl = src & 255, dl = dst & 255;
    float w = Ablk[(((size_t)b << 8) + sl) * NPG + dl];   // A[src, dst]
    atomicAdd(&Adj[(((size_t)b << 8) + dl) * NPG + sl], w);
}

// ---------------- GEMM kernels ----------------------------------------------
__global__ __launch_bounds__(256) void k_gemm_nn(const float* __restrict__ A,
                                                 const float* __restrict__ W,
                                                 float* __restrict__ C) {
    __shared__ float As[BM][LDA_S];
    __shared__ float Bs[BK][LDB_S];
    int m0 = blockIdx.y * BM, n0 = blockIdx.x * BN, z = blockIdx.z;
    float acc[4][4];
    #pragma unroll
    for (int i = 0; i < 4; i++)
        #pragma unroll
        for (int j = 0; j < 4; j++) acc[i][j] = 0.f;
    mm_nn(A + (size_t)m0 * DDIM, DDIM, W + (size_t)z * DDIM * DDIM + n0, DDIM, DDIM, As, Bs, acc);
    float* Cg = C + (size_t)z * NNODE * DDIM;
    int tx = threadIdx.x & 15, ty = threadIdx.x >> 4;
    #pragma unroll
    for (int i = 0; i < 4; i++)
        #pragma unroll
        for (int j = 0; j < 4; j++)
            Cg[(size_t)(m0 + ty * 4 + i) * DDIM + n0 + tx * 4 + j] = acc[i][j];
}

__global__ __launch_bounds__(256) void k_corr(const float* __restrict__ x,
                                              const float* __restrict__ sc,
                                              float* __restrict__ Ablk) {
    __shared__ float As[BM][LDA_S];
    __shared__ float Bs[BK][LDB_S];
    int m0 = blockIdx.y * BM, n0 = blockIdx.x * BN, b = blockIdx.z;
    const float* base = x + (size_t)b * NPG * DDIM;
    float acc[4][4];
    #pragma unroll
    for (int i = 0; i < 4; i++)
        #pragma unroll
        for (int j = 0; j < 4; j++) acc[i][j] = 0.f;
    mm_nt(base + (size_t)m0 * DDIM, DDIM, base + (size_t)n0 * DDIM, DDIM, DDIM, As, Bs, acc);
    int tx = threadIdx.x & 15, ty = threadIdx.x >> 4;
    #pragma unroll
    for (int i = 0; i < 4; i++) {
        int li = m0 + ty * 4 + i;
        float si = sc[b * NPG + li];
        #pragma unroll
        for (int j = 0; j < 4; j++) {
            int lj = n0 + tx * 4 + j;
            Ablk[((size_t)b * NPG + li) * NPG + lj] = acc[i][j] * si * sc[b * NPG + lj];
        }
    }
}

__global__ __launch_bounds__(256) void k_aggr(const float* __restrict__ Adj,
                                              const float* __restrict__ G,
                                              const float* __restrict__ bg,
                                              float* __restrict__ Hout) {
    __shared__ float As[BM][LDA_S];
    __shared__ float Bs[BK][LDB_S];
    int m0 = blockIdx.y * BM, n0 = blockIdx.x * BN, b = blockIdx.z;
    float acc[4][4];
    #pragma unroll
    for (int i = 0; i < 4; i++)
        #pragma unroll
        for (int j = 0; j < 4; j++) acc[i][j] = 0.f;
    #pragma unroll
    for (int t = 0; t < 3; t++) {
        const float* Ag = Adj + ((size_t)(t * BGRP + b)) * NPG * NPG + (size_t)m0 * NPG;
        const float* Bg = G + (size_t)t * NNODE * DDIM + (size_t)b * NPG * DDIM + n0;
        mm_nn(Ag, NPG, Bg, DDIM, DDIM, As, Bs, acc);
    }
    int tx = threadIdx.x & 15, ty = threadIdx.x >> 4;
    #pragma unroll
    for (int j = 0; j < 4; j++) {
        int jj = n0 + tx * 4 + j;
        float bias = bg[jj] + bg[DDIM + jj] + bg[2 * DDIM + jj];
        #pragma unroll
        for (int i = 0; i < 4; i++) {
            int li = m0 + ty * 4 + i;
            Hout[((size_t)b * NPG + li) * DDIM + jj] = fmaxf(acc[i][j] + bias, 0.f);
        }
    }
}

__global__ __launch_bounds__(256) void k_ahat(const float* __restrict__ HT,
                                              const float* __restrict__ Hn,
                                              float* __restrict__ Ablk) {
    __shared__ float As[BM][LDA_S];
    __shared__ float Bs[BK][LDB_S];
    int m0 = blockIdx.y * BM, n0 = blockIdx.x * BN, b = blockIdx.z;
    float acc[4][4];
    #pragma unroll
    for (int i = 0; i < 4; i++)
        #pragma unroll
        for (int j = 0; j < 4; j++) acc[i][j] = 0.f;
    mm_nt(HT + ((size_t)b * NPG + m0) * DDIM, DDIM,
          Hn + ((size_t)b * NPG + n0) * DDIM, DDIM, DDIM, As, Bs, acc);
    int tx = threadIdx.x & 15, ty = threadIdx.x >> 4;
    #pragma unroll
    for (int i = 0; i < 4; i++) {
        int li = m0 + ty * 4 + i;
        #pragma unroll
        for (int j = 0; j < 4; j++) {
            int lj = n0 + tx * 4 + j;
            size_t idx = ((size_t)b * NPG + li) * NPG + lj;
            float sig = 1.0f / (1.0f + expf(-acc[i][j]));
            Ablk[idx] = 0.5f * Ablk[idx] + 0.5f * sig;
        }
    }
}

// ---------------- final maps ------------------------------------------------
__global__ __launch_bounds__(256) void k_final(const float* __restrict__ Ablk,
                                               const float* __restrict__ emf,
                                               const float* __restrict__ pmf,
                                               float* __restrict__ out) {
    int b = blockIdx.x;
    __shared__ float ems[NPG], pms[NPG];
    __shared__ float me[NPG], mp[NPG];
    __shared__ float red[256];
    int t = threadIdx.x;
    ems[t] = emf[b * NPG + t];
    pms[t] = pmf[b * NPG + t];
    __syncthreads();
    int warp = t >> 5, lane = t & 31;
    for (int r = warp; r < NPG; r += 8) {
        const float* row = Ablk + ((size_t)b * NPG + r) * NPG;
        float s = 0.f, es = 0.f, ps = 0.f;
        for (int j = lane; j < NPG; j += 32) {
            float a = row[j];
            s += a; es += a * ems[j]; ps += a * pms[j];
        }
        #pragma unroll
        for (int o = 16; o; o >>= 1) {
            s  += __shfl_xor_sync(0xffffffffu, s, o);
            es += __shfl_xor_sync(0xffffffffu, es, o);
            ps += __shfl_xor_sync(0xffffffffu, ps, o);
        }
        if (!lane) { me[r] = s - ps; mp[r] = s - es; }  // map_entity, map_pattern
    }
    __syncthreads();
    for (int pass = 0; pass < 2; pass++) {
        float v = pass ? mp[t] : me[t];
        red[t] = v; __syncthreads();
        for (int s2 = 128; s2; s2 >>= 1) {
            if (t < s2) red[t] = fminf(red[t], red[t + s2]);
            __syncthreads();
        }
        float mn = red[0]; __syncthreads();
        red[t] = v; __syncthreads();
        for (int s2 = 128; s2; s2 >>= 1) {
            if (t < s2) red[t] = fmaxf(red[t], red[t + s2]);
            __syncthreads();
        }
        float mx = red[0]; __syncthreads();
        float u = (v - mn) / (mx - mn + ZERO_EPS);
        red[t] = u; __syncthreads();
        for (int s2 = 128; s2; s2 >>= 1) {
            if (t < s2) red[t] += red[t + s2];
            __syncthreads();
        }
        float sm = red[0]; __syncthreads();
        out[pass * (BGRP * NPG) + b * NPG + t] = u / (sm + ZERO_EPS);
    }
}

// ---------------- host ------------------------------------------------------
extern "C" void kernel_launch(void* const* d_in, const int* in_sizes, int n_in,
                              void* d_out, int out_size) {
    const float*     x    = (const float*)d_in[0];
    const int*       ei_e = (const int*)d_in[1];
    const float*     ew_e = (const float*)d_in[2];
    const int*       ei_p = (const int*)d_in[3];
    const float*     ew_p = (const float*)d_in[4];
    const int*       ei_o = (const int*)d_in[5];
    const float*     ew_o = (const float*)d_in[6];
    const unsigned char* em = (const unsigned char*)d_in[7];
    const unsigned char* pm = (const unsigned char*)d_in[8];
    const float*     Wg   = (const float*)d_in[9];
    const float*     bg   = (const float*)d_in[10];
    const float*     Td   = (const float*)d_in[11];
    float* out = (float*)d_out;

    float *H0, *H1, *G, *HT, *Ablk, *Adj, *nrm, *rinv, *sc, *svec, *emf, *pmf;
    cudaGetSymbolAddress((void**)&H0,   g_H0);
    cudaGetSymbolAddress((void**)&H1,   g_H1);
    cudaGetSymbolAddress((void**)&G,    g_G);
    cudaGetSymbolAddress((void**)&HT,   g_HT);
    cudaGetSymbolAddress((void**)&Ablk, g_Ablk);
    cudaGetSymbolAddress((void**)&Adj,  g_Adj);
    cudaGetSymbolAddress((void**)&nrm,  g_nrm);
    cudaGetSymbolAddress((void**)&rinv, g_rinv);
    cudaGetSymbolAddress((void**)&sc,   g_sc);
    cudaGetSymbolAddress((void**)&svec, g_svec);
    cudaGetSymbolAddress((void**)&emf,  g_emf);
    cudaGetSymbolAddress((void**)&pmf,  g_pmf);

    const size_t ADJ1 = (size_t)BGRP * NPG * NPG;

    // --- masks (dtype-agnostic decode) --------------------------------------
    k_mask_detect<<<1, 256>>>(em, pm);
    k_mask_decode<<<NMASK / 256, 256>>>(em, pm, emf, pmf);

    // --- prologue: norms, s-vector, dinv factors, block-diagonal A0 ---------
    k_zero<<<4096, 256>>>(Adj, (int)(3 * ADJ1));
    k_zero<<<1, 256>>>(svec, DDIM);
    k_rownorm<<<NNODE / 8, 256>>>(x, nrm, rinv);
    k_colsum<<<64, 256>>>(x, rinv, svec);
    k_scale<<<NNODE / 8, 256>>>(x, rinv, svec, sc);
    k_corr<<<dim3(4, 4, BGRP), 256>>>(x, sc, Ablk);

    // --- layer-0 adjacency from input edge weights --------------------------
    k_scatter_w<<<NEDGE / 256, 256>>>(ei_e, ew_e, Adj);
    k_scatter_w<<<NEDGE / 256, 256>>>(ei_p, ew_p, Adj + ADJ1);
    k_scatter_w<<<NEDGE / 256, 256>>>(ei_o, ew_o, Adj + 2 * ADJ1);

    // --- layer 0 ------------------------------------------------------------
    k_gemm_nn<<<dim3(4, 128, 3), 256>>>(x, Wg, G);
    k_aggr<<<dim3(4, 4, BGRP), 256>>>(Adj, G, bg, H0);
    k_gemm_nn<<<dim3(4, 128, 1), 256>>>(H0, Td, HT);
    k_ahat<<<dim3(4, 4, BGRP), 256>>>(HT, H0, Ablk);

    // --- layer-1 adjacency from updated A ------------------------------------
    k_zero<<<4096, 256>>>(Adj, (int)(3 * ADJ1));
    k_scatter_A<<<NEDGE / 256, 256>>>(ei_e, Ablk, Adj);
    k_scatter_A<<<NEDGE / 256, 256>>>(ei_p, Ablk, Adj + ADJ1);
    k_scatter_A<<<NEDGE / 256, 256>>>(ei_o, Ablk, Adj + 2 * ADJ1);

    // --- layer 1 ------------------------------------------------------------
    k_gemm_nn<<<dim3(4, 128, 3), 256>>>(H0, Wg + 3 * DDIM * DDIM, G);
    k_aggr<<<dim3(4, 4, BGRP), 256>>>(Adj, G, bg + 3 * DDIM, H1);
    k_gemm_nn<<<dim3(4, 128, 1), 256>>>(H1, Td + DDIM * DDIM, HT);
    k_ahat<<<dim3(4, 4, BGRP), 256>>>(HT, H1, Ablk);

    // --- final maps ----------------------------------------------------------
    k_final<<<BGRP, 256>>>(Ablk, emf, pmf, out);
}

// round 4
// speedup vs baseline: 1.2212x; 1.2212x over previous
#include <cuda_runtime.h>
#include <math.h>

#define NNODE 8192
#define DDIM  256
#define NPG   256
#define BGRP  32
#define NEDGE 131072
#define NMASK (BGRP * NPG)
#define ZERO_EPS 1e-8f

#define TBM 128
#define TBN 128
#define TBK 8

// ---------------- scratch ----------------------------------------------------
__device__ float g_H0[NNODE * DDIM];
__device__ float g_H1[NNODE * DDIM];
__device__ float g_G[3 * NNODE * DDIM];
__device__ float g_HT[NNODE * DDIM];
__device__ float g_Ablk[BGRP * NPG * NPG];
__device__ float g_Adj[3 * BGRP * NPG * NPG];
__device__ float g_nrm[NNODE];
__device__ float g_rinv[NNODE];
__device__ float g_sc[NNODE];
__device__ float g_svec[DDIM];
__device__ float g_emf[NMASK];
__device__ float g_pmf[NMASK];
__device__ int   g_mask_mode;

// ---------------- 128x128x8 double-buffered mainloop -------------------------
// A: row-major M x K slab (Ag points at tile row 0), lda.
// NT=false: B row-major K x N (Bg at tile col 0 already offset), ldb.
// NT=true : B row-major N x K (Bg at tile's first row), ldb; computes A @ B^T.
template<bool NT>
__device__ __forceinline__ void mm128(const float* __restrict__ Ag, int lda,
                                      const float* __restrict__ Bg, int ldb,
                                      int K,
                                      float (*As)[TBK][TBM], float (*Bs)[TBK][TBN],
                                      float acc[8][8])
{
    const int tid = threadIdx.x;
    const int am  = tid >> 1, akq = (tid & 1) << 2;   // A (and NT-B) loader coords
    const int bk  = tid >> 5, bn  = (tid & 31) << 2;  // NN-B loader coords
    const int tx  = tid & 15, ty  = tid >> 4;

    const int S = K / TBK;
    float4 ar, br;

    // prologue: stage 0
    ar = *(const float4*)(Ag + (size_t)am * lda + akq);
    if (NT) br = *(const float4*)(Bg + (size_t)am * ldb + akq);
    else    br = *(const float4*)(Bg + (size_t)bk * ldb + bn);
    As[0][akq + 0][am] = ar.x; As[0][akq + 1][am] = ar.y;
    As[0][akq + 2][am] = ar.z; As[0][akq + 3][am] = ar.w;
    if (NT) {
        Bs[0][akq + 0][am] = br.x; Bs[0][akq + 1][am] = br.y;
        Bs[0][akq + 2][am] = br.z; Bs[0][akq + 3][am] = br.w;
    } else {
        *(float4*)&Bs[0][bk][bn] = br;
    }
    __syncthreads();

    for (int s = 0; s < S; s++) {
        const int buf = s & 1;
        if (s + 1 < S) {
            ar = *(const float4*)(Ag + (size_t)am * lda + (s + 1) * TBK + akq);
            if (NT) br = *(const float4*)(Bg + (size_t)am * ldb + (s + 1) * TBK + akq);
            else    br = *(const float4*)(Bg + (size_t)((s + 1) * TBK + bk) * ldb + bn);
        }
        #pragma unroll
        for (int kk = 0; kk < TBK; kk++) {
            float4 a0 = *(const float4*)&As[buf][kk][ty * 4];
            float4 a1 = *(const float4*)&As[buf][kk][64 + ty * 4];
            float4 b0 = *(const float4*)&Bs[buf][kk][tx * 4];
            float4 b1 = *(const float4*)&Bs[buf][kk][64 + tx * 4];
            float a[8] = {a0.x, a0.y, a0.z, a0.w, a1.x, a1.y, a1.z, a1.w};
            float b[8] = {b0.x, b0.y, b0.z, b0.w, b1.x, b1.y, b1.z, b1.w};
            #pragma unroll
            for (int i = 0; i < 8; i++)
                #pragma unroll
                for (int j = 0; j < 8; j++)
                    acc[i][j] += a[i] * b[j];
        }
        if (s + 1 < S) {
            const int nb = buf ^ 1;
            As[nb][akq + 0][am] = ar.x; As[nb][akq + 1][am] = ar.y;
            As[nb][akq + 2][am] = ar.z; As[nb][akq + 3][am] = ar.w;
            if (NT) {
                Bs[nb][akq + 0][am] = br.x; Bs[nb][akq + 1][am] = br.y;
                Bs[nb][akq + 2][am] = br.z; Bs[nb][akq + 3][am] = br.w;
            } else {
                *(float4*)&Bs[nb][bk][bn] = br;
            }
        }
        __syncthreads();
    }
}

#define ROWI(i) ( ((i) < 4) ? (ty * 4 + (i)) : (64 + ty * 4 + (i) - 4) )

// ---------------- GEMM kernels ----------------------------------------------
// C[z] = A(NNODE x D) @ W[z](D x D)
__global__ __launch_bounds__(256, 2) void k_gemm_nn(const float* __restrict__ A,
                                                    const float* __restrict__ W,
                                                    float* __restrict__ C) {
    __shared__ float As[2][TBK][TBM];
    __shared__ float Bs[2][TBK][TBN];
    int m0 = blockIdx.y * TBM, n0 = blockIdx.x * TBN, z = blockIdx.z;
    float acc[8][8];
    #pragma unroll
    for (int i = 0; i < 8; i++)
        #pragma unroll
        for (int j = 0; j < 8; j++) acc[i][j] = 0.f;
    mm128<false>(A + (size_t)m0 * DDIM, DDIM,
                 W + (size_t)z * DDIM * DDIM + n0, DDIM, DDIM, As, Bs, acc);
    float* Cg = C + (size_t)z * NNODE * DDIM;
    int tx = threadIdx.x & 15, ty = threadIdx.x >> 4;
    #pragma unroll
    for (int i = 0; i < 8; i++) {
        int r = m0 + ROWI(i);
        *(float4*)&Cg[(size_t)r * DDIM + n0 + tx * 4] =
            make_float4(acc[i][0], acc[i][1], acc[i][2], acc[i][3]);
        *(float4*)&Cg[(size_t)r * DDIM + n0 + 64 + tx * 4] =
            make_float4(acc[i][4], acc[i][5], acc[i][6], acc[i][7]);
    }
}

// Ablk[b] = (X_b X_b^T) * sc_i * sc_j
__global__ __launch_bounds__(256, 2) void k_corr(const float* __restrict__ x,
                                                 const float* __restrict__ sc,
                                                 float* __restrict__ Ablk) {
    __shared__ float As[2][TBK][TBM];
    __shared__ float Bs[2][TBK][TBN];
    int m0 = blockIdx.y * TBM, n0 = blockIdx.x * TBN, b = blockIdx.z;
    const float* base = x + (size_t)b * NPG * DDIM;
    float acc[8][8];
    #pragma unroll
    for (int i = 0; i < 8; i++)
        #pragma unroll
        for (int j = 0; j < 8; j++) acc[i][j] = 0.f;
    mm128<true>(base + (size_t)m0 * DDIM, DDIM,
                base + (size_t)n0 * DDIM, DDIM, DDIM, As, Bs, acc);
    int tx = threadIdx.x & 15, ty = threadIdx.x >> 4;
    #pragma unroll
    for (int i = 0; i < 8; i++) {
        int li = m0 + ROWI(i);
        float si = sc[b * NPG + li];
        float* row = Ablk + ((size_t)b * NPG + li) * NPG;
        #pragma unroll
        for (int jh = 0; jh < 2; jh++) {
            int c0 = n0 + jh * 64 + tx * 4;
            float4 v;
            v.x = acc[i][jh * 4 + 0] * si * sc[b * NPG + c0 + 0];
            v.y = acc[i][jh * 4 + 1] * si * sc[b * NPG + c0 + 1];
            v.z = acc[i][jh * 4 + 2] * si * sc[b * NPG + c0 + 2];
            v.w = acc[i][jh * 4 + 3] * si * sc[b * NPG + c0 + 3];
            *(float4*)&row[c0] = v;
        }
    }
}

// Hout[b] = relu( sum_t Adj_t[b] @ G_t[b] + sum_t bias_t )
__global__ __launch_bounds__(256, 2) void k_aggr(const float* __restrict__ Adj,
                                                 const float* __restrict__ G,
                                                 const float* __restrict__ bg,
                                                 float* __restrict__ Hout) {
    __shared__ float As[2][TBK][TBM];
    __shared__ float Bs[2][TBK][TBN];
    int m0 = blockIdx.y * TBM, n0 = blockIdx.x * TBN, b = blockIdx.z;
    float acc[8][8];
    #pragma unroll
    for (int i = 0; i < 8; i++)
        #pragma unroll
        for (int j = 0; j < 8; j++) acc[i][j] = 0.f;
    #pragma unroll
    for (int t = 0; t < 3; t++) {
        const float* Ag = Adj + ((size_t)(t * BGRP + b)) * NPG * NPG + (size_t)m0 * NPG;
        const float* Bg = G + (size_t)t * NNODE * DDIM + (size_t)b * NPG * DDIM + n0;
        mm128<false>(Ag, NPG, Bg, DDIM, DDIM, As, Bs, acc);
    }
    int tx = threadIdx.x & 15, ty = threadIdx.x >> 4;
    #pragma unroll
    for (int i = 0; i < 8; i++) {
        int li = m0 + ROWI(i);
        float* row = Hout + ((size_t)b * NPG + li) * DDIM;
        #pragma unroll
        for (int jh = 0; jh < 2; jh++) {
            int c0 = n0 + jh * 64 + tx * 4;
            float4 v;
            v.x = fmaxf(acc[i][jh * 4 + 0] + bg[c0 + 0] + bg[DDIM + c0 + 0] + bg[2 * DDIM + c0 + 0], 0.f);
            v.y = fmaxf(acc[i][jh * 4 + 1] + bg[c0 + 1] + bg[DDIM + c0 + 1] + bg[2 * DDIM + c0 + 1], 0.f);
            v.z = fmaxf(acc[i][jh * 4 + 2] + bg[c0 + 2] + bg[DDIM + c0 + 2] + bg[2 * DDIM + c0 + 2], 0.f);
            v.w = fmaxf(acc[i][jh * 4 + 3] + bg[c0 + 3] + bg[DDIM + c0 + 3] + bg[2 * DDIM + c0 + 3], 0.f);
            *(float4*)&row[c0] = v;
        }
    }
}

// Ablk[b] = 0.5*Ablk[b] + 0.5*sigmoid( HT_b @ Hn_b^T )
__global__ __launch_bounds__(256, 2) void k_ahat(const float* __restrict__ HT,
                                                 const float* __restrict__ Hn,
                                                 float* __restrict__ Ablk) {
    __shared__ float As[2][TBK][TBM];
    __shared__ float Bs[2][TBK][TBN];
    int m0 = blockIdx.y * TBM, n0 = blockIdx.x * TBN, b = blockIdx.z;
    float acc[8][8];
    #pragma unroll
    for (int i = 0; i < 8; i++)
        #pragma unroll
        for (int j = 0; j < 8; j++) acc[i][j] = 0.f;
    mm128<true>(HT + ((size_t)b * NPG + m0) * DDIM, DDIM,
                Hn + ((size_t)b * NPG + n0) * DDIM, DDIM, DDIM, As, Bs, acc);
    int tx = threadIdx.x & 15, ty = threadIdx.x >> 4;
    #pragma unroll
    for (int i = 0; i < 8; i++) {
        int li = m0 + ROWI(i);
        float* row = Ablk + ((size_t)b * NPG + li) * NPG;
        #pragma unroll
        for (int jh = 0; jh < 2; jh++) {
            int c0 = n0 + jh * 64 + tx * 4;
            float4 old = *(const float4*)&row[c0];
            float4 v;
            v.x = 0.5f * old.x + 0.5f / (1.0f + expf(-acc[i][jh * 4 + 0]));
            v.y = 0.5f * old.y + 0.5f / (1.0f + expf(-acc[i][jh * 4 + 1]));
            v.z = 0.5f * old.z + 0.5f / (1.0f + expf(-acc[i][jh * 4 + 2]));
            v.w = 0.5f * old.w + 0.5f / (1.0f + expf(-acc[i][jh * 4 + 3]));
            *(float4*)&row[c0] = v;
        }
    }
}

// ---------------- small kernels ---------------------------------------------
__global__ void k_mask_detect(const unsigned char* __restrict__ em,
                              const unsigned char* __restrict__ pm) {
    __shared__ int nz[4];
    if (threadIdx.x < 4) nz[threadIdx.x] = 0;
    __syncthreads();
    int loc[4] = {0, 0, 0, 0};
    for (int i = threadIdx.x; i < NMASK; i += 256) {
        if (em[i]) loc[i & 3]++;
        if (pm[i]) loc[i & 3]++;
    }
    #pragma unroll
    for (int j = 0; j < 4; j++) if (loc[j]) atomicAdd(&nz[j], loc[j]);
    __syncthreads();
    if (threadIdx.x == 0) {
        int mode;
        if (nz[1] > 0) mode = 0;
        else if (nz[0] > 0) mode = 1;
        else mode = 2;
        g_mask_mode = mode;
    }
}

__global__ void k_mask_decode(const unsigned char* __restrict__ em,
                              const unsigned char* __restrict__ pm,
                              float* __restrict__ emf, float* __restrict__ pmf) {
    int i = blockIdx.x * blockDim.x + threadIdx.x;
    if (i >= NMASK) return;
    int mode = g_mask_mode;
    float e, p;
    if (mode == 0) {
        e = em[i] ? 1.f : 0.f;
        p = pm[i] ? 1.f : 0.f;
    } else if (mode == 1) {
        e = ((const int*)em)[i] ? 1.f : 0.f;
        p = ((const int*)pm)[i] ? 1.f : 0.f;
    } else {
        e = (((const float*)em)[i] != 0.f) ? 1.f : 0.f;
        p = (((const float*)pm)[i] != 0.f) ? 1.f : 0.f;
    }
    emf[i] = e; pmf[i] = p;
}

__global__ void k_rownorm(const float* __restrict__ x, float* __restrict__ nrm,
                          float* __restrict__ rinv) {
    int warp = (blockIdx.x * blockDim.x + threadIdx.x) >> 5;
    int lane = threadIdx.x & 31;
    if (warp >= NNODE) return;
    const float* r = x + (size_t)warp * DDIM;
    float s = 0.f;
    for (int j = lane; j < DDIM; j += 32) { float v = r[j]; s += v * v; }
    #pragma unroll
    for (int o = 16; o; o >>= 1) s += __shfl_xor_sync(0xffffffffu, s, o);
    if (!lane) { float n = sqrtf(s); nrm[warp] = n; rinv[warp] = 1.0f / n; }
}

__global__ void k_colsum(const float* __restrict__ x, const float* __restrict__ rinv,
                         float* __restrict__ svec) {
    int d = threadIdx.x;
    int r0 = blockIdx.x * 128;
    float acc = 0.f;
    for (int r = r0; r < r0 + 128; r++)
        acc += x[(size_t)r * DDIM + d] * rinv[r];
    atomicAdd(&svec[d], acc);
}

__global__ void k_scale(const float* __restrict__ x, const float* __restrict__ rinv,
                        const float* __restrict__ svec, float* __restrict__ sc) {
    int warp = (blockIdx.x * blockDim.x + threadIdx.x) >> 5;
    int lane = threadIdx.x & 31;
    if (warp >= NNODE) return;
    const float* r = x + (size_t)warp * DDIM;
    float dot = 0.f;
    for (int j = lane; j < DDIM; j += 32) dot += r[j] * svec[j];
    #pragma unroll
    for (int o = 16; o; o >>= 1) dot += __shfl_xor_sync(0xffffffffu, dot, o);
    if (!lane) {
        float rowsum = dot * rinv[warp];
        sc[warp] = rsqrtf(fabsf(rowsum) + ZERO_EPS) * rinv[warp];
    }
}

__global__ void k_scatter_w(const int* __restrict__ ei, const float* __restrict__ ew,
                            float* __restrict__ Adj) {
    int e = blockIdx.x * blockDim.x + threadIdx.x;
    if (e >= NEDGE) return;
    int src = ei[e], dst = ei[NEDGE + e];
    int b = src >> 8, sl = src & 255, dl = dst & 255;
    atomicAdd(&Adj[(((size_t)b << 8) + dl) * NPG + sl], ew[e]);
}

__global__ void k_scatter_A(const int* __restrict__ ei, const float* __restrict__ Ablk,
                            float* __restrict__ Adj) {
    int e = blockIdx.x * blockDim.x + threadIdx.x;
    if (e >= NEDGE) return;
    int src = ei[e], dst = ei[NEDGE + e];
    int b = src >> 8, sl = src & 255, dl = dst & 255;
    float w = Ablk[(((size_t)b << 8) + sl) * NPG + dl];
    atomicAdd(&Adj[(((size_t)b << 8) + dl) * NPG + sl], w);
}

// ---------------- final maps ------------------------------------------------
__global__ __launch_bounds__(256) void k_final(const float* __restrict__ Ablk,
                                               const float* __restrict__ emf,
                                               const float* __restrict__ pmf,
                                               float* __restrict__ out) {
    int b = blockIdx.x;
    __shared__ float ems[NPG], pms[NPG];
    __shared__ float me[NPG], mp[NPG];
    __shared__ float red[256];
    int t = threadIdx.x;
    ems[t] = emf[b * NPG + t];
    pms[t] = pmf[b * NPG + t];
    __syncthreads();
    int warp = t >> 5, lane = t & 31;
    for (int r = warp; r < NPG; r += 8) {
        const float* row = Ablk + ((size_t)b * NPG + r) * NPG;
        float s = 0.f, es = 0.f, ps = 0.f;
        for (int j = lane; j < NPG; j += 32) {
            float a = row[j];
            s += a; es += a * ems[j]; ps += a * pms[j];
        }
        #pragma unroll
        for (int o = 16; o; o >>= 1) {
            s  += __shfl_xor_sync(0xffffffffu, s, o);
            es += __shfl_xor_sync(0xffffffffu, es, o);
            ps += __shfl_xor_sync(0xffffffffu, ps, o);
        }
        if (!lane) { me[r] = s - ps; mp[r] = s - es; }
    }
    __syncthreads();
    for (int pass = 0; pass < 2; pass++) {
        float v = pass ? mp[t] : me[t];
        red[t] = v; __syncthreads();
        for (int s2 = 128; s2; s2 >>= 1) {
            if (t < s2) red[t] = fminf(red[t], red[t + s2]);
            __syncthreads();
        }
        float mn = red[0]; __syncthreads();
        red[t] = v; __syncthreads();
        for (int s2 = 128; s2; s2 >>= 1) {
            if (t < s2) red[t] = fmaxf(red[t], red[t + s2]);
            __syncthreads();
        }
        float mx = red[0]; __syncthreads();
        float u = (v - mn) / (mx - mn + ZERO_EPS);
        red[t] = u; __syncthreads();
        for (int s2 = 128; s2; s2 >>= 1) {
            if (t < s2) red[t] += red[t + s2];
            __syncthreads();
        }
        float sm = red[0]; __syncthreads();
        out[pass * (BGRP * NPG) + b * NPG + t] = u / (sm + ZERO_EPS);
    }
}

// ---------------- host ------------------------------------------------------
extern "C" void kernel_launch(void* const* d_in, const int* in_sizes, int n_in,
                              void* d_out, int out_size) {
    const float*     x    = (const float*)d_in[0];
    const int*       ei_e = (const int*)d_in[1];
    const float*     ew_e = (const float*)d_in[2];
    const int*       ei_p = (const int*)d_in[3];
    const float*     ew_p = (const float*)d_in[4];
    const int*       ei_o = (const int*)d_in[5];
    const float*     ew_o = (const float*)d_in[6];
    const unsigned char* em = (const unsigned char*)d_in[7];
    const unsigned char* pm = (const unsigned char*)d_in[8];
    const float*     Wg   = (const float*)d_in[9];
    const float*     bg   = (const float*)d_in[10];
    const float*     Td   = (const float*)d_in[11];
    float* out = (float*)d_out;

    float *H0, *H1, *G, *HT, *Ablk, *Adj, *nrm, *rinv, *sc, *svec, *emf, *pmf;
    cudaGetSymbolAddress((void**)&H0,   g_H0);
    cudaGetSymbolAddress((void**)&H1,   g_H1);
    cudaGetSymbolAddress((void**)&G,    g_G);
    cudaGetSymbolAddress((void**)&HT,   g_HT);
    cudaGetSymbolAddress((void**)&Ablk, g_Ablk);
    cudaGetSymbolAddress((void**)&Adj,  g_Adj);
    cudaGetSymbolAddress((void**)&nrm,  g_nrm);
    cudaGetSymbolAddress((void**)&rinv, g_rinv);
    cudaGetSymbolAddress((void**)&sc,   g_sc);
    cudaGetSymbolAddress((void**)&svec, g_svec);
    cudaGetSymbolAddress((void**)&emf,  g_emf);
    cudaGetSymbolAddress((void**)&pmf,  g_pmf);

    const size_t ADJ1 = (size_t)BGRP * NPG * NPG;

    // masks
    k_mask_detect<<<1, 256>>>(em, pm);
    k_mask_decode<<<NMASK / 256, 256>>>(em, pm, emf, pmf);

    // prologue
    cudaMemsetAsync(Adj, 0, 3 * ADJ1 * sizeof(float));
    cudaMemsetAsync(svec, 0, DDIM * sizeof(float));
    k_rownorm<<<NNODE / 8, 256>>>(x, nrm, rinv);
    k_colsum<<<64, 256>>>(x, rinv, svec);
    k_scale<<<NNODE / 8, 256>>>(x, rinv, svec, sc);
    k_corr<<<dim3(2, 2, BGRP), 256>>>(x, sc, Ablk);

    // layer-0 adjacency
    k_scatter_w<<<NEDGE / 256, 256>>>(ei_e, ew_e, Adj);
    k_scatter_w<<<NEDGE / 256, 256>>>(ei_p, ew_p, Adj + ADJ1);
    k_scatter_w<<<NEDGE / 256, 256>>>(ei_o, ew_o, Adj + 2 * ADJ1);

    // layer 0
    k_gemm_nn<<<dim3(2, 64, 3), 256>>>(x, Wg, G);
    k_aggr<<<dim3(2, 2, BGRP), 256>>>(Adj, G, bg, H0);
    k_gemm_nn<<<dim3(2, 64, 1), 256>>>(H0, Td, HT);
    k_ahat<<<dim3(2, 2, BGRP), 256>>>(HT, H0, Ablk);

    // layer-1 adjacency
    cudaMemsetAsync(Adj, 0, 3 * ADJ1 * sizeof(float));
    k_scatter_A<<<NEDGE / 256, 256>>>(ei_e, Ablk, Adj);
    k_scatter_A<<<NEDGE / 256, 256>>>(ei_p, Ablk, Adj + ADJ1);
    k_scatter_A<<<NEDGE / 256, 256>>>(ei_o, Ablk, Adj + 2 * ADJ1);

    // layer 1
    k_gemm_nn<<<dim3(2, 64, 3), 256>>>(H0, Wg + 3 * DDIM * DDIM, G);
    k_aggr<<<dim3(2, 2, BGRP), 256>>>(Adj, G, bg + 3 * DDIM, H1);
    k_gemm_nn<<<dim3(2, 64, 1), 256>>>(H1, Td + DDIM * DDIM, HT);
    k_ahat<<<dim3(2, 2, BGRP), 256>>>(HT, H1, Ablk);

    // final maps
    k_final<<<BGRP, 256>>>(Ablk, emf, pmf, out);
}